// round 9
// baseline (speedup 1.0000x reference)
#include <cuda_runtime.h>
#include <cuda_bf16.h>

// Problem shape (fixed by the dataset): image (2048, 8192, 4) fp32 -> points (2048*8192, 3) fp32
#define H 2048
#define W 8192
#define NPIX (H * W)
#define PIX_PER_THREAD 4
#define NTHREADS (NPIX / PIX_PER_THREAD)   // 4,194,304
#define BLOCK 256

// ---------------------------------------------------------------------------
// Compile-time trig tables: 12-term Taylor in double (|err| < 2e-13 on [-pi,pi]),
// baked into an initialized __device__ global. No prologue kernel at runtime.
// ---------------------------------------------------------------------------
constexpr double PI_D = 3.141592653589793238462643383279502884;

constexpr double tsin(double x) {
    double x2 = x * x, term = x, sum = x;
    for (int k = 1; k <= 12; ++k) {
        term *= -x2 / (double)((2 * k) * (2 * k + 1));
        sum += term;
    }
    return sum;
}
constexpr double tcos(double x) {
    double x2 = x * x, term = 1.0, sum = 1.0;
    for (int k = 1; k <= 12; ++k) {
        term *= -x2 / (double)((2 * k - 1) * (2 * k));
        sum += term;
    }
    return sum;
}

struct alignas(16) Tables {
    float cy[W];   // cos(yaw_j)
    float sy[W];   // -sin(yaw_j)  (minus folded in)
    float sp[H];   // sin(pitch_i)
};

constexpr Tables make_tables() {
    Tables t{};
    const double FOV_DOWN_ABS = 15.0 / 180.0 * PI_D;
    const double FOV_SPAN     = 30.0 / 180.0 * PI_D;
    for (int j = 0; j < W; ++j) {
        double yaw = (double)j / (double)W * (2.0 * PI_D) - PI_D;
        t.cy[j] = (float)tcos(yaw);
        t.sy[j] = (float)(-tsin(yaw));
    }
    for (int i = 0; i < H; ++i) {
        double pitch = (1.0 - (double)i / (double)H) * FOV_SPAN - FOV_DOWN_ABS;
        t.sp[i] = (float)tsin(pitch);
    }
    return t;
}

__device__ constexpr Tables g_tab = make_tables();

// ---------------------------------------------------------------------------
// Main streaming kernel (unchanged access pattern: proven 6.34 TB/s, at the
// full-chip LTS throughput ceiling).
// ---------------------------------------------------------------------------
__global__ void __launch_bounds__(BLOCK)
project_kernel(const float4* __restrict__ im, float4* __restrict__ out) {
    int t = blockIdx.x * BLOCK + threadIdx.x;      // 0 .. NTHREADS-1
    int p0 = t << 2;                               // first pixel handled by this thread
    int row = p0 >> 13;                            // / W  (W = 8192)
    int c4  = t & 2047;                            // (p0 & 8191) / 4 : float4 index into tables

    float sp = g_tab.sp[row];
    const float4* __restrict__ cy4 = reinterpret_cast<const float4*>(g_tab.cy);
    const float4* __restrict__ sy4 = reinterpret_cast<const float4*>(g_tab.sy);
    float4 cy = __ldg(cy4 + c4);
    float4 sy = __ldg(sy4 + c4);

    // 4 consecutive pixels, depth is the .w channel
    float4 v0 = im[p0 + 0];
    float4 v1 = im[p0 + 1];
    float4 v2 = im[p0 + 2];
    float4 v3 = im[p0 + 3];
    float d0 = v0.w, d1 = v1.w, d2 = v2.w, d3 = v3.w;

    float x0 = d0 * cy.x, y0 = d0 * sy.x, z0 = d0 * sp;
    float x1 = d1 * cy.y, y1 = d1 * sy.y, z1 = d1 * sp;
    float x2 = d2 * cy.z, y2 = d2 * sy.z, z2 = d2 * sp;
    float x3 = d3 * cy.w, y3 = d3 * sy.w, z3 = d3 * sp;

    // 12 contiguous output floats -> 3 dense float4 stores
    int ob = 3 * t;
    out[ob + 0] = make_float4(x0, y0, z0, x1);
    out[ob + 1] = make_float4(y1, z1, x2, y2);
    out[ob + 2] = make_float4(z2, x3, y3, z3);
}

extern "C" void kernel_launch(void* const* d_in, const int* in_sizes, int n_in,
                              void* d_out, int out_size) {
    (void)in_sizes; (void)n_in; (void)out_size;
    const float4* im = (const float4*)d_in[0];
    float4* out = (float4*)d_out;

    // Single-node graph: tables are baked into the module image at compile time.
    project_kernel<<<NTHREADS / BLOCK, BLOCK>>>(im, out);
}

// round 10
// speedup vs baseline: 1.4428x; 1.4428x over previous
#include <cuda_runtime.h>
#include <cuda_bf16.h>

// Problem shape (fixed by the dataset): image (2048, 8192, 4) fp32 -> points (2048*8192, 3) fp32
#define H 2048
#define W 8192
#define NPIX (H * W)
#define PIX_PER_THREAD 4
#define NTHREADS (NPIX / PIX_PER_THREAD)   // 4,194,304
#define BLOCK 256

// ---------------------------------------------------------------------------
// Compile-time trig tables: 12-term Taylor in double (|err| < 2e-13 on [-pi,pi]).
// IMPORTANT: the global is NON-const (constexpr initializer only), forcing
// .global placement. R9 showed that a `__device__ constexpr` (const) table is
// routed through the constant-bank/LDC path, whose half-rate divergent-address
// port throttled the kernel to 106 us.
// ---------------------------------------------------------------------------
constexpr double PI_D = 3.141592653589793238462643383279502884;

constexpr double tsin(double x) {
    double x2 = x * x, term = x, sum = x;
    for (int k = 1; k <= 12; ++k) {
        term *= -x2 / (double)((2 * k) * (2 * k + 1));
        sum += term;
    }
    return sum;
}
constexpr double tcos(double x) {
    double x2 = x * x, term = 1.0, sum = 1.0;
    for (int k = 1; k <= 12; ++k) {
        term *= -x2 / (double)((2 * k - 1) * (2 * k));
        sum += term;
    }
    return sum;
}

struct alignas(16) Tables {
    float cy[W];   // cos(yaw_j)
    float sy[W];   // -sin(yaw_j)  (minus folded in)
    float sp[H];   // sin(pitch_i)
};

constexpr Tables make_tables() {
    Tables t{};
    const double FOV_DOWN_ABS = 15.0 / 180.0 * PI_D;
    const double FOV_SPAN     = 30.0 / 180.0 * PI_D;
    for (int j = 0; j < W; ++j) {
        double yaw = (double)j / (double)W * (2.0 * PI_D) - PI_D;
        t.cy[j] = (float)tcos(yaw);
        t.sy[j] = (float)(-tsin(yaw));
    }
    for (int i = 0; i < H; ++i) {
        double pitch = (1.0 - (double)i / (double)H) * FOV_SPAN - FOV_DOWN_ABS;
        t.sp[i] = (float)tsin(pitch);
    }
    return t;
}

// Non-const __device__ global, constexpr-initialized -> .global section.
__device__ Tables g_tab = make_tables();

// ---------------------------------------------------------------------------
// Main streaming kernel (R8-proven access pattern: 6.34 TB/s).
// ---------------------------------------------------------------------------
__global__ void __launch_bounds__(BLOCK)
project_kernel(const float4* __restrict__ im, float4* __restrict__ out) {
    int t = blockIdx.x * BLOCK + threadIdx.x;      // 0 .. NTHREADS-1
    int p0 = t << 2;                               // first pixel handled by this thread
    int row = p0 >> 13;                            // / W  (W = 8192)
    int c4  = t & 2047;                            // (p0 & 8191) / 4 : float4 index into tables

    float sp = g_tab.sp[row];
    const float4* __restrict__ cy4 = reinterpret_cast<const float4*>(g_tab.cy);
    const float4* __restrict__ sy4 = reinterpret_cast<const float4*>(g_tab.sy);
    float4 cy = __ldg(cy4 + c4);
    float4 sy = __ldg(sy4 + c4);

    // 4 consecutive pixels, depth is the .w channel
    float4 v0 = im[p0 + 0];
    float4 v1 = im[p0 + 1];
    float4 v2 = im[p0 + 2];
    float4 v3 = im[p0 + 3];
    float d0 = v0.w, d1 = v1.w, d2 = v2.w, d3 = v3.w;

    float x0 = d0 * cy.x, y0 = d0 * sy.x, z0 = d0 * sp;
    float x1 = d1 * cy.y, y1 = d1 * sy.y, z1 = d1 * sp;
    float x2 = d2 * cy.z, y2 = d2 * sy.z, z2 = d2 * sp;
    float x3 = d3 * cy.w, y3 = d3 * sy.w, z3 = d3 * sp;

    // 12 contiguous output floats -> 3 dense float4 stores
    int ob = 3 * t;
    out[ob + 0] = make_float4(x0, y0, z0, x1);
    out[ob + 1] = make_float4(y1, z1, x2, y2);
    out[ob + 2] = make_float4(z2, x3, y3, z3);
}

extern "C" void kernel_launch(void* const* d_in, const int* in_sizes, int n_in,
                              void* d_out, int out_size) {
    (void)in_sizes; (void)n_in; (void)out_size;
    const float4* im = (const float4*)d_in[0];
    float4* out = (float4*)d_out;

    // Single-node graph: tables baked into the module's .global image.
    project_kernel<<<NTHREADS / BLOCK, BLOCK>>>(im, out);
}